// round 17
// baseline (speedup 1.0000x reference)
#include <cuda_runtime.h>
#include <cuda_fp16.h>
#include <cstdint>

// Problem constants
#define B_SZ   256
#define LDIM   257                 // N+1
#define M_MAP  66049               // 257*257  (GEMM K)
#define H_DIM  512
#define C_OUT  4

// GEMM tiling (legacy fp16 mma m16n8k16)
#define BM 256                     // full batch
#define BN 128                     // 4 N tiles
#define BK 32                      // 2 k16 steps per chunk
#define SPLITS 37                  // 4*37 = 148 CTAs = one wave
#define CPS 56
#define TOTAL_CHUNKS 2065
#define THREADS 640                // 16 MMA warps + 4 producer warps

// smem geometry
#define AROW 40                    // halfs per A row (32 + 8 pad) = 80B
#define BROW 36                    // floats per B row (32 + 4 pad) = 144B
#define BSTAGE_BYTES (BN * BROW * 4)          // 18432
#define ABUF_BYTES   (BM * AROW * 2)          // 20480
#define SM_B   0
#define SM_A   (3 * BSTAGE_BYTES)             // 55296
#define SM_IT  (SM_A + 2 * ABUF_BYTES)        // 96256 (float2 itab[257])
#define SMEM_BYTES (SM_IT + 2104)             // 98360 -> pad

// Scratch
__device__ __align__(16) uint2 g_tbl[LDIM * B_SZ];                     // fp16 (Ha,A1),(Ra,0)
__device__ __align__(16) float g_part[(size_t)SPLITS * B_SZ * H_DIM];  // split-K partials
__device__ float g_consts[5];

__device__ __forceinline__ float frcp(float x) {
    float r; asm("rcp.approx.f32 %0, %1;" : "=f"(r) : "f"(x)); return r;
}
__device__ __forceinline__ float ftanh(float x) {
    float r; asm("tanh.approx.f32 %0, %1;" : "=f"(r) : "f"(x)); return r;
}
__device__ __forceinline__ uint32_t smem_u32(const void* p) {
    return (uint32_t)__cvta_generic_to_shared(p);
}
__device__ __forceinline__ void cp4z(uint32_t dst, const float* src, int src_bytes) {
    asm volatile("cp.async.ca.shared.global [%0], [%1], 4, %2;\n" :: "r"(dst), "l"(src), "r"(src_bytes));
}
__device__ __forceinline__ uint32_t pack_h2(float lo, float hi) {
    uint32_t u;
    asm("cvt.rn.f16x2.f32 %0, %1, %2;" : "=r"(u) : "f"(hi), "f"(lo));
    return u;
}
__device__ __forceinline__ float2 unpack_h2(uint32_t u) {
    __half2 h = *reinterpret_cast<__half2*>(&u);
    return __half22float2(h);
}

// ---------------------------------------------------------------------------
// Phase 0a: fold 1x1-conv + eval-mode BN
// ---------------------------------------------------------------------------
__global__ void prep_kernel(const float* __restrict__ conv_w, const float* __restrict__ conv_b,
                            const float* __restrict__ bn_g,  const float* __restrict__ bn_b,
                            const float* __restrict__ bn_m,  const float* __restrict__ bn_v) {
    if (threadIdx.x == 0) {
        float s = bn_g[0] * rsqrtf(bn_v[0] + 1e-5f);
        g_consts[0] = conv_w[0] * s;
        g_consts[1] = conv_w[1] * s;
        g_consts[2] = conv_w[2] * s;
        g_consts[3] = conv_w[3] * s;
        g_consts[4] = (conv_b[0] - bn_m[0]) * s + bn_b[0];
    }
}

// ---------------------------------------------------------------------------
// Phase 0b: per-(j,b) fp16 table: (Ha = a0/2, A1 = a1), (Ra = 1/(a1+eps), 0)
// ---------------------------------------------------------------------------
__global__ void pre_kernel(const float* __restrict__ x1) {
    const int j = blockIdx.x;     // 0..256
    const int b = threadIdx.x;    // 0..255
    const float a0 = (j == 0) ? 0.0f : x1[b * (LDIM - 1) + j - 1];
    const float a1 = (j == 0) ? 1.0f : a0;
    float Ra = frcp(a1 + 1e-10f);
    Ra = fmaxf(fminf(Ra, 60000.0f), -60000.0f);   // fp16-safe; tanh saturated there anyway
    uint2 v;
    v.x = pack_h2(0.5f * a0, a1);
    v.y = pack_h2(Ra, 0.0f);
    g_tbl[j * B_SZ + b] = v;
}

// ---------------------------------------------------------------------------
// Fused GEMM: 16 MMA warps + 4 producer warps (one per SMSP).
// Producers compute the fp16 A tile for chunk c+1 while MMA consumes chunk c.
// ---------------------------------------------------------------------------
__device__ __forceinline__ void mma_f16(float c[4], const uint32_t a[4], const uint32_t b[2]) {
    asm volatile(
        "mma.sync.aligned.m16n8k16.row.col.f32.f16.f16.f32 "
        "{%0,%1,%2,%3}, {%4,%5,%6,%7}, {%8,%9}, {%0,%1,%2,%3};\n"
        : "+f"(c[0]), "+f"(c[1]), "+f"(c[2]), "+f"(c[3])
        : "r"(a[0]), "r"(a[1]), "r"(a[2]), "r"(a[3]), "r"(b[0]), "r"(b[1]));
}

__device__ __forceinline__ void ldsm_x4(uint32_t a[4], uint32_t ptr) {
    asm volatile("ldmatrix.sync.aligned.m8n8.x4.shared.b16 {%0,%1,%2,%3}, [%4];"
                 : "=r"(a[0]), "=r"(a[1]), "=r"(a[2]), "=r"(a[3]) : "r"(ptr));
}

__device__ __forceinline__ void load_B(char* sm, int stage, int gchunk, int bn0,
                                       const float* __restrict__ W, int tid) {
    const int k0 = gchunk * BK;
    uint32_t sB = smem_u32(sm + SM_B + stage * BSTAGE_BYTES);
#pragma unroll
    for (int r = 0; r < 8; r++) {
        int flat = tid + r * 512;
        int n = flat >> 5, k = flat & 31;
        int ke = k0 + k;
        int bytes = (ke < M_MAP) ? 4 : 0;
        const float* src = &W[(size_t)(bn0 + n) * M_MAP + (bytes ? ke : 0)];
        cp4z(sB + (n * BROW + k) * 4, src, bytes);
    }
}

// Producer: 128 threads build A[256 x 32] fp16 tile for chunk c.
// Thread t: k-pair kp = t&15 (cols 2kp, 2kp+1); b range [ (t>>4)*32, +32 ).
__device__ __forceinline__ void produce_A(char* sm, int bufIdx, int c,
                                          const float2* __restrict__ itab,
                                          float c0, float c1, float c2, float c3, float cb,
                                          int pt) {
    char* Abuf = sm + SM_A + bufIdx * ABUF_BYTES;
    const int kp = pt & 15;
    const int b0 = (pt >> 4) * 32;
    const int k0 = c * BK;
    const int ke = k0 + 2 * kp;
    const int ko = ke + 1;
    const bool ve = ke < M_MAP;
    const bool vo = ko < M_MAP;
    const int ie = ve ? ke / LDIM : 0;
    const int io = vo ? ko / LDIM : 0;
    const int je = ve ? ke - ie * LDIM : 0;
    const int jo = vo ? ko - io * LDIM : 0;
    const float2 pe = itab[ie];   // (hb, hb1) for even k's i
    const float2 po = itab[io];

    const uint4* __restrict__ Te = reinterpret_cast<const uint4*>(g_tbl + je * B_SZ + b0);
    const uint4* __restrict__ To = reinterpret_cast<const uint4*>(g_tbl + jo * B_SZ + b0);

#pragma unroll 4
    for (int q = 0; q < 16; q++) {
        const uint4 ue = Te[q];   // two b entries for k-even
        const uint4 uo = To[q];   // two b entries for k-odd
#pragma unroll
        for (int h = 0; h < 2; h++) {
            float y_e = 0.0f, y_o = 0.0f;
            if (ve) {
                const float2 ha_a1 = unpack_h2(h ? ue.z : ue.x);
                const float2 ra    = unpack_h2(h ? ue.w : ue.y);
                const float t1 = ftanh(pe.x + ha_a1.x);
                const float t2 = ftanh(pe.x - ha_a1.x);
                const float t3 = ftanh(pe.y * ha_a1.y);
                const float t4 = ftanh(pe.y * ra.x);
                y_e = cb + c0 * t1 + c1 * t2 + c2 * t3 + c3 * t4;
                y_e = (y_e >= 0.0f) ? y_e : 0.1f * y_e;
            }
            if (vo) {
                const float2 ha_a1 = unpack_h2(h ? uo.z : uo.x);
                const float2 ra    = unpack_h2(h ? uo.w : uo.y);
                const float t1 = ftanh(po.x + ha_a1.x);
                const float t2 = ftanh(po.x - ha_a1.x);
                const float t3 = ftanh(po.y * ha_a1.y);
                const float t4 = ftanh(po.y * ra.x);
                y_o = cb + c0 * t1 + c1 * t2 + c2 * t3 + c3 * t4;
                y_o = (y_o >= 0.0f) ? y_o : 0.1f * y_o;
            }
            const int b = b0 + 2 * q + h;
            *reinterpret_cast<uint32_t*>(Abuf + b * (AROW * 2) + kp * 4) = pack_h2(y_e, y_o);
        }
    }
}

__global__ void __launch_bounds__(THREADS, 1) gemm_kernel(const float* __restrict__ W,
                                                          const float* __restrict__ x3) {
    extern __shared__ char sm[];
    float2* itab = reinterpret_cast<float2*>(sm + SM_IT);

    const int bn0   = blockIdx.x * BN;     // 4 N tiles
    const int split = blockIdx.y;          // 37 K splits
    const int cbeg  = split * CPS;
    const int cend  = (cbeg + CPS < TOTAL_CHUNKS) ? cbeg + CPS : TOTAL_CHUNKS;
    const int nch   = cend - cbeg;

    const int tid  = threadIdx.x;
    const int wid  = tid >> 5, lane = tid & 31;
    const bool isMMA = (tid < 512);
    const int wm   = wid & 3,  wn   = wid >> 2;    // 4 x 4 (MMA warps only)
    const int g    = lane >> 2, tg  = lane & 3;
    const int ldsmRow = lane & 15;
    const int ldsmCol = (lane >> 4) * 8;

    // per-i table (hb = b0/2, hb1 = b1/2)
    if (tid < LDIM) {
        const float b0 = (tid == 0) ? 0.0f : x3[tid - 1];
        const float b1 = (tid == 0) ? 1.0f : b0;
        itab[tid] = make_float2(0.5f * b0, 0.5f * b1);
    }
    // folded conv consts (producers use)
    const float c0 = 0.5f * g_consts[0], c1 = 0.5f * g_consts[1];
    const float c2 = 0.5f * g_consts[2], c3 = 0.5f * g_consts[3];
    const float cb = g_consts[4] + c0 + c1 + c2 + c3;
    __syncthreads();   // itab ready

    float acc[4][4][4];
#pragma unroll
    for (int mi = 0; mi < 4; mi++)
#pragma unroll
        for (int ni = 0; ni < 4; ni++)
#pragma unroll
            for (int q = 0; q < 4; q++) acc[mi][ni][q] = 0.0f;

    // Prologue
    if (isMMA) {
        load_B(sm, 0, cbeg + 0, bn0, W, tid);
        asm volatile("cp.async.commit_group;\n" ::: "memory");
        if (nch > 1)
            load_B(sm, 1, cbeg + 1, bn0, W, tid);
        asm volatile("cp.async.commit_group;\n" ::: "memory");
    } else {
        produce_A(sm, 0, cbeg, itab, c0, c1, c2, c3, cb, tid - 512);
    }

    for (int cc = 0; cc < nch; ++cc) {
        if (isMMA)
            asm volatile("cp.async.wait_group 1;\n" ::: "memory");
        __syncthreads();   // A(cc) + B(cc) visible to everyone

        if (isMMA) {
            if (cc + 2 < nch)
                load_B(sm, (cc + 2) % 3, cbeg + cc + 2, bn0, W, tid);
            asm volatile("cp.async.commit_group;\n" ::: "memory");

            const float* Sb = reinterpret_cast<const float*>(sm + SM_B + (cc % 3) * BSTAGE_BYTES);
            const uint32_t aBase = smem_u32(sm + SM_A + (cc & 1) * ABUF_BYTES) +
                2 * ((wm * 64 + ldsmRow) * AROW + ldsmCol);

#pragma unroll
            for (int ks = 0; ks < 2; ++ks) {
                uint32_t bfr[4][2];
#pragma unroll
                for (int ni = 0; ni < 4; ni++) {
                    const int n0 = wn * 32 + ni * 8 + g;
                    const int kb = ks * 16 + tg * 2;
                    const float2 f01 = *reinterpret_cast<const float2*>(&Sb[n0 * BROW + kb]);
                    const float2 f23 = *reinterpret_cast<const float2*>(&Sb[n0 * BROW + kb + 8]);
                    bfr[ni][0] = pack_h2(f01.x, f01.y);
                    bfr[ni][1] = pack_h2(f23.x, f23.y);
                }
#pragma unroll
                for (int mi = 0; mi < 4; mi++) {
                    uint32_t a[4];
                    ldsm_x4(a, aBase + 2 * (mi * 16 * AROW + ks * 16));
#pragma unroll
                    for (int ni = 0; ni < 4; ni++)
                        mma_f16(acc[mi][ni], a, bfr[ni]);
                }
            }
        } else {
            if (cc + 1 < nch)
                produce_A(sm, (cc + 1) & 1, cbeg + cc + 1, itab, c0, c1, c2, c3, cb, tid - 512);
        }
    }

    // Deterministic partial store (MMA warps only)
    if (isMMA) {
        float* __restrict__ P = g_part + (size_t)split * (B_SZ * H_DIM);
#pragma unroll
        for (int mi = 0; mi < 4; mi++) {
#pragma unroll
            for (int ni = 0; ni < 4; ni++) {
                const int row = wm * 64 + mi * 16 + g;
                const int col = bn0 + wn * 32 + ni * 8 + tg * 2;
                *reinterpret_cast<float2*>(&P[(size_t)row * H_DIM + col]) =
                    make_float2(acc[mi][ni][0], acc[mi][ni][1]);
                *reinterpret_cast<float2*>(&P[(size_t)(row + 8) * H_DIM + col]) =
                    make_float2(acc[mi][ni][2], acc[mi][ni][3]);
            }
        }
    }
}

// ---------------------------------------------------------------------------
// Phase 3: reduce 37 splits + bias -> ReLU -> 512->4 head
// ---------------------------------------------------------------------------
__global__ void __launch_bounds__(512) head_kernel(const float* __restrict__ fc_b,
                                                   const float* __restrict__ out_w,
                                                   const float* __restrict__ out_b,
                                                   float* __restrict__ out) {
    const int b = blockIdx.x;
    const int h = threadIdx.x;
    const int wid = h >> 5, lane = h & 31;

    float v = 0.0f;
#pragma unroll
    for (int sp = 0; sp < SPLITS; ++sp)
        v += g_part[(size_t)sp * (B_SZ * H_DIM) + (size_t)b * H_DIM + h];
    v += fc_b[h];
    v = fmaxf(v, 0.0f);

    float p[4];
#pragma unroll
    for (int c = 0; c < 4; ++c) p[c] = v * out_w[c * H_DIM + h];

#pragma unroll
    for (int off = 16; off > 0; off >>= 1)
#pragma unroll
        for (int c = 0; c < 4; ++c) p[c] += __shfl_down_sync(0xffffffffu, p[c], off);

    __shared__ float red[4][16];
    if (lane == 0) {
#pragma unroll
        for (int c = 0; c < 4; ++c) red[c][wid] = p[c];
    }
    __syncthreads();
    if (h < 4) {
        float s = 0.0f;
#pragma unroll
        for (int w = 0; w < 16; ++w) s += red[h][w];
        out[b * C_OUT + h] = s + out_b[h];
    }
}

// ---------------------------------------------------------------------------
extern "C" void kernel_launch(void* const* d_in, const int* in_sizes, int n_in,
                              void* d_out, int out_size) {
    const float* x1     = (const float*)d_in[0];
    const float* x3     = (const float*)d_in[1];
    const float* conv_w = (const float*)d_in[2];
    const float* conv_b = (const float*)d_in[3];
    const float* bn_g   = (const float*)d_in[4];
    const float* bn_b   = (const float*)d_in[5];
    const float* bn_m   = (const float*)d_in[6];
    const float* bn_v   = (const float*)d_in[7];
    const float* fc_w   = (const float*)d_in[8];
    const float* fc_b   = (const float*)d_in[9];
    const float* out_w  = (const float*)d_in[10];
    const float* out_b  = (const float*)d_in[11];
    float* out = (float*)d_out;

    cudaFuncSetAttribute(gemm_kernel, cudaFuncAttributeMaxDynamicSharedMemorySize, SMEM_BYTES);

    prep_kernel<<<1, 32>>>(conv_w, conv_b, bn_g, bn_b, bn_m, bn_v);
    pre_kernel<<<LDIM, B_SZ>>>(x1);
    dim3 grid(H_DIM / BN, SPLITS);
    gemm_kernel<<<grid, THREADS, SMEM_BYTES>>>(fc_w, x3);
    head_kernel<<<B_SZ, 512>>>(fc_b, out_w, out_b, out);
}